// round 3
// baseline (speedup 1.0000x reference)
#include <cuda_runtime.h>
#include <cuda_bf16.h>

#define NMAX   100000
#define EMAX   640000
#define LATDIM 128
#define F2     64          // float2 per row
#define SCAN_B 1024

// ---- scratch (__device__ globals; allocation-free rule) --------------------
__device__ float g_bufA[(size_t)NMAX * LATDIM];
__device__ float g_bufB[(size_t)NMAX * LATDIM];
__device__ int   g_cnt[NMAX];
__device__ int   g_ofs[NMAX];
__device__ int   g_rowstart[NMAX];
__device__ int   g_bsum[SCAN_B];
__device__ int   g_bpref[SCAN_B];
__device__ uint2 g_edges[EMAX];

// ---------------------------------------------------------------------------
// LayerNorm: warp per node, lane owns one float4
// ---------------------------------------------------------------------------
__global__ void ln_kernel(const float* __restrict__ in, float* __restrict__ out,
                          int n_nodes) {
    int gw   = (blockIdx.x * blockDim.x + threadIdx.x) >> 5;
    int lane = threadIdx.x & 31;
    if (gw >= n_nodes) return;

    float4 v = reinterpret_cast<const float4*>(in)[(size_t)gw * 32 + lane];

    float s  = v.x + v.y + v.z + v.w;
    float ss = v.x * v.x + v.y * v.y + v.z * v.z + v.w * v.w;
    #pragma unroll
    for (int o = 16; o > 0; o >>= 1) {
        s  += __shfl_xor_sync(0xFFFFFFFFu, s,  o);
        ss += __shfl_xor_sync(0xFFFFFFFFu, ss, o);
    }
    float mu  = s * (1.0f / LATDIM);
    float var = ss * (1.0f / LATDIM) - mu * mu;
    float inv = rsqrtf(var + 1e-5f);

    v.x = (v.x - mu) * inv; v.y = (v.y - mu) * inv;
    v.z = (v.z - mu) * inv; v.w = (v.w - mu) * inv;

    reinterpret_cast<float4*>(out)[(size_t)gw * 32 + lane] = v;
}

// ---------------------------------------------------------------------------
// CSR build
// ---------------------------------------------------------------------------
__global__ void zero_counts_kernel(int n_nodes) {
    int i = blockIdx.x * blockDim.x + threadIdx.x;
    if (i < n_nodes) { g_cnt[i] = 0; g_ofs[i] = 0; }
}

__global__ void hist_kernel(const int* __restrict__ row, int n_edges) {
    int e      = blockIdx.x * blockDim.x + threadIdx.x;
    int stride = gridDim.x * blockDim.x;
    for (; e < n_edges; e += stride) atomicAdd(&g_cnt[row[e]], 1);
}

// warp-shuffle based block scan (exclusive out), emits block total
__global__ void scan1_kernel(int n_nodes) {
    __shared__ int wsum[32];
    int t = threadIdx.x, lane = t & 31, wid = t >> 5;
    int i = blockIdx.x * SCAN_B + t;
    int v = (i < n_nodes) ? g_cnt[i] : 0;

    int x = v;
    #pragma unroll
    for (int o = 1; o < 32; o <<= 1) {
        int y = __shfl_up_sync(0xFFFFFFFFu, x, o);
        if (lane >= o) x += y;
    }
    if (lane == 31) wsum[wid] = x;
    __syncthreads();
    if (wid == 0) {
        int s = wsum[lane];
        #pragma unroll
        for (int o = 1; o < 32; o <<= 1) {
            int y = __shfl_up_sync(0xFFFFFFFFu, s, o);
            if (lane >= o) s += y;
        }
        wsum[lane] = s;
    }
    __syncthreads();
    int incl = x + (wid ? wsum[wid - 1] : 0);
    if (i < n_nodes) g_rowstart[i] = incl - v;
    if (t == SCAN_B - 1) g_bsum[blockIdx.x] = incl;
}

__global__ void scan2_kernel(int n_blocks) {
    __shared__ int wsum[32];
    int t = threadIdx.x, lane = t & 31, wid = t >> 5;
    int v = (t < n_blocks) ? g_bsum[t] : 0;

    int x = v;
    #pragma unroll
    for (int o = 1; o < 32; o <<= 1) {
        int y = __shfl_up_sync(0xFFFFFFFFu, x, o);
        if (lane >= o) x += y;
    }
    if (lane == 31) wsum[wid] = x;
    __syncthreads();
    if (wid == 0) {
        int s = wsum[lane];
        #pragma unroll
        for (int o = 1; o < 32; o <<= 1) {
            int y = __shfl_up_sync(0xFFFFFFFFu, s, o);
            if (lane >= o) s += y;
        }
        wsum[lane] = s;
    }
    __syncthreads();
    int incl = x + (wid ? wsum[wid - 1] : 0);
    g_bpref[t] = incl - v;
}

__global__ void scatter_kernel(const int* __restrict__ row,
                               const int* __restrict__ col,
                               const float* __restrict__ val,
                               int n_edges) {
    int e      = blockIdx.x * blockDim.x + threadIdx.x;
    int stride = gridDim.x * blockDim.x;
    for (; e < n_edges; e += stride) {
        int r    = row[e];
        int base = g_rowstart[r] + g_bpref[r >> 10];
        int k    = atomicAdd(&g_ofs[r], 1);
        g_edges[base + k] = make_uint2((unsigned)col[e], __float_as_uint(val[e]));
    }
}

// ---------------------------------------------------------------------------
// SpMM: 2 warps per row (feature-split), lane owns one float2 (64 f2/row).
// FINAL==0 : y = acc                         (layers 1,2 — no out traffic)
// FINAL==1 : out = acc + y1[r] + y2[r]       (layer 3; streaming hints on
//                                             out / y1 so x stays in L2)
// ---------------------------------------------------------------------------
template <int FINAL>
__global__ void spmm_row_kernel(const float* __restrict__ x,
                                float* __restrict__ y,
                                const float* __restrict__ y1,
                                float* __restrict__ out,
                                int n_nodes) {
    int gw = (blockIdx.x * blockDim.x + threadIdx.x) >> 5;
    int r  = gw >> 1;
    if (r >= n_nodes) return;
    int half = gw & 1;
    int lane = threadIdx.x & 31;
    size_t fofs = (size_t)half * 32 + lane;   // float2 index within row

    int base = g_rowstart[r] + g_bpref[r >> 10];
    int deg  = g_cnt[r];

    const float2* x2 = reinterpret_cast<const float2*>(x);
    float2 acc = make_float2(0.f, 0.f);

    for (int s = 0; s < deg; s += 32) {
        int m = deg - s; if (m > 32) m = 32;
        uint2 ev = make_uint2(0u, 0u);
        if (lane < m) ev = __ldg(&g_edges[base + s + lane]);
        #pragma unroll 8
        for (int k = 0; k < m; ++k) {
            int   c = __shfl_sync(0xFFFFFFFFu, (int)ev.x, k);
            float v = __uint_as_float(__shfl_sync(0xFFFFFFFFu, (int)ev.y, k));
            float2 xv = __ldg(x2 + (size_t)c * F2 + fofs);
            acc.x += v * xv.x;
            acc.y += v * xv.y;
        }
    }

    size_t oi = (size_t)r * F2 + fofs;
    if (FINAL == 0) {
        reinterpret_cast<float2*>(y)[oi] = acc;   // keep in L2 for next layer
    } else {
        float2 a = __ldcs(reinterpret_cast<const float2*>(y1) + oi);  // y1: evict-first
        float2 b = __ldg (reinterpret_cast<const float2*>(x)  + oi);  // y2 row (gather src, L2-hot)
        acc.x += a.x + b.x;
        acc.y += a.y + b.y;
        __stcs(reinterpret_cast<float2*>(out) + oi, acc);             // out: streaming
    }
}

// ---------------------------------------------------------------------------
// Launcher
// ---------------------------------------------------------------------------
extern "C" void kernel_launch(void* const* d_in, const int* in_sizes, int n_in,
                              void* d_out, int out_size) {
    const float* embeds  = (const float*)d_in[0];
    const int*   adj_row = (const int*)d_in[1];
    const int*   adj_col = (const int*)d_in[2];
    const float* adj_val = (const float*)d_in[3];

    int n_nodes = in_sizes[0] / LATDIM;
    int n_edges = in_sizes[1];

    float* bufA = nullptr;
    float* bufB = nullptr;
    cudaGetSymbolAddress((void**)&bufA, g_bufA);
    cudaGetSymbolAddress((void**)&bufB, g_bufB);
    float* out = (float*)d_out;

    const int TPB = 256;
    int ln_blocks   = (n_nodes * 32 + TPB - 1) / TPB;
    int spmm_blocks = (n_nodes * 2 * 32 + TPB - 1) / TPB;   // 2 warps/row
    int scan_blocks = (n_nodes + SCAN_B - 1) / SCAN_B;

    // LayerNorm: embeds -> bufA (x0)
    ln_kernel<<<ln_blocks, TPB>>>(embeds, bufA, n_nodes);

    // CSR build (reused by all 3 layers)
    zero_counts_kernel<<<(n_nodes + TPB - 1) / TPB, TPB>>>(n_nodes);
    hist_kernel<<<1024, TPB>>>(adj_row, n_edges);
    scan1_kernel<<<scan_blocks, SCAN_B>>>(n_nodes);
    scan2_kernel<<<1, SCAN_B>>>(scan_blocks);
    scatter_kernel<<<1024, TPB>>>(adj_row, adj_col, adj_val, n_edges);

    // Layer 1: y1 = A * x0          (bufA -> bufB)
    spmm_row_kernel<0><<<spmm_blocks, TPB>>>(bufA, bufB, nullptr, nullptr, n_nodes);
    // Layer 2: y2 = A * y1          (bufB -> bufA, overwrites x0)
    spmm_row_kernel<0><<<spmm_blocks, TPB>>>(bufB, bufA, nullptr, nullptr, n_nodes);
    // Layer 3: out = A*y2 + y1 + y2 (gather bufA, add bufB + bufA rows)
    spmm_row_kernel<1><<<spmm_blocks, TPB>>>(bufA, nullptr, bufB, out, n_nodes);
}

// round 4
// speedup vs baseline: 1.4740x; 1.4740x over previous
#include <cuda_runtime.h>
#include <cuda_bf16.h>

#define NMAX   100000
#define EMAX   640000
#define LATDIM 128
#define VEC    32          // float4 per row
#define SCAN_B 1024

// ---- scratch (__device__ globals; allocation-free rule) --------------------
__device__ float g_bufA[(size_t)NMAX * LATDIM];
__device__ float g_bufB[(size_t)NMAX * LATDIM];
__device__ int   g_cnt[NMAX];
__device__ int   g_ofs[NMAX];
__device__ int   g_rowstart[NMAX];
__device__ int   g_bsum[SCAN_B];
__device__ int   g_bpref[SCAN_B];
__device__ uint2 g_edges[EMAX];

// ---------------------------------------------------------------------------
// LayerNorm: warp per node, lane owns one float4
// ---------------------------------------------------------------------------
__global__ void ln_kernel(const float* __restrict__ in, float* __restrict__ out,
                          int n_nodes) {
    int gw   = (blockIdx.x * blockDim.x + threadIdx.x) >> 5;
    int lane = threadIdx.x & 31;
    if (gw >= n_nodes) return;

    float4 v = reinterpret_cast<const float4*>(in)[(size_t)gw * VEC + lane];

    float s  = v.x + v.y + v.z + v.w;
    float ss = v.x * v.x + v.y * v.y + v.z * v.z + v.w * v.w;
    #pragma unroll
    for (int o = 16; o > 0; o >>= 1) {
        s  += __shfl_xor_sync(0xFFFFFFFFu, s,  o);
        ss += __shfl_xor_sync(0xFFFFFFFFu, ss, o);
    }
    float mu  = s * (1.0f / LATDIM);
    float var = ss * (1.0f / LATDIM) - mu * mu;
    float inv = rsqrtf(var + 1e-5f);

    v.x = (v.x - mu) * inv; v.y = (v.y - mu) * inv;
    v.z = (v.z - mu) * inv; v.w = (v.w - mu) * inv;

    reinterpret_cast<float4*>(out)[(size_t)gw * VEC + lane] = v;
}

// ---------------------------------------------------------------------------
// CSR build
// ---------------------------------------------------------------------------
__global__ void zero_counts_kernel(int n_nodes) {
    int i = blockIdx.x * blockDim.x + threadIdx.x;
    if (i < n_nodes) { g_cnt[i] = 0; g_ofs[i] = 0; }
}

__global__ void hist_kernel(const int* __restrict__ row, int n_edges) {
    int e      = blockIdx.x * blockDim.x + threadIdx.x;
    int stride = gridDim.x * blockDim.x;
    for (; e < n_edges; e += stride) atomicAdd(&g_cnt[row[e]], 1);
}

// warp-shuffle block scan (exclusive out), emits block total
__global__ void scan1_kernel(int n_nodes) {
    __shared__ int wsum[32];
    int t = threadIdx.x, lane = t & 31, wid = t >> 5;
    int i = blockIdx.x * SCAN_B + t;
    int v = (i < n_nodes) ? g_cnt[i] : 0;

    int x = v;
    #pragma unroll
    for (int o = 1; o < 32; o <<= 1) {
        int y = __shfl_up_sync(0xFFFFFFFFu, x, o);
        if (lane >= o) x += y;
    }
    if (lane == 31) wsum[wid] = x;
    __syncthreads();
    if (wid == 0) {
        int s = wsum[lane];
        #pragma unroll
        for (int o = 1; o < 32; o <<= 1) {
            int y = __shfl_up_sync(0xFFFFFFFFu, s, o);
            if (lane >= o) s += y;
        }
        wsum[lane] = s;
    }
    __syncthreads();
    int incl = x + (wid ? wsum[wid - 1] : 0);
    if (i < n_nodes) g_rowstart[i] = incl - v;
    if (t == SCAN_B - 1) g_bsum[blockIdx.x] = incl;
}

__global__ void scan2_kernel(int n_blocks) {
    __shared__ int wsum[32];
    int t = threadIdx.x, lane = t & 31, wid = t >> 5;
    int v = (t < n_blocks) ? g_bsum[t] : 0;

    int x = v;
    #pragma unroll
    for (int o = 1; o < 32; o <<= 1) {
        int y = __shfl_up_sync(0xFFFFFFFFu, x, o);
        if (lane >= o) x += y;
    }
    if (lane == 31) wsum[wid] = x;
    __syncthreads();
    if (wid == 0) {
        int s = wsum[lane];
        #pragma unroll
        for (int o = 1; o < 32; o <<= 1) {
            int y = __shfl_up_sync(0xFFFFFFFFu, s, o);
            if (lane >= o) s += y;
        }
        wsum[lane] = s;
    }
    __syncthreads();
    int incl = x + (wid ? wsum[wid - 1] : 0);
    g_bpref[t] = incl - v;
}

__global__ void scatter_kernel(const int* __restrict__ row,
                               const int* __restrict__ col,
                               const float* __restrict__ val,
                               int n_edges) {
    int e      = blockIdx.x * blockDim.x + threadIdx.x;
    int stride = gridDim.x * blockDim.x;
    for (; e < n_edges; e += stride) {
        int r    = row[e];
        int base = g_rowstart[r] + g_bpref[r >> 10];
        int k    = atomicAdd(&g_ofs[r], 1);
        g_edges[base + k] = make_uint2((unsigned)col[e], __float_as_uint(val[e]));
    }
}

// ---------------------------------------------------------------------------
// SpMM: 1 warp per row, lane owns one float4. Register accumulation, no atomics.
// FINAL==0 : y = acc                    (layers 1,2 — zero `out` traffic)
// FINAL==1 : out = acc + y1[r] + x[r]   (layer 3; x row == y2; streaming hints
//                                        on y1/out keep the gather set in L2)
// ---------------------------------------------------------------------------
template <int FINAL>
__global__ void __launch_bounds__(256)
spmm_row_kernel(const float* __restrict__ x,
                float* __restrict__ y,
                const float* __restrict__ y1,
                float* __restrict__ out,
                int n_nodes) {
    int r = (blockIdx.x * blockDim.x + threadIdx.x) >> 5;
    if (r >= n_nodes) return;
    int lane = threadIdx.x & 31;

    int base = g_rowstart[r] + g_bpref[r >> 10];
    int deg  = g_cnt[r];

    const float4* x4 = reinterpret_cast<const float4*>(x);
    float4 acc = make_float4(0.f, 0.f, 0.f, 0.f);

    for (int s = 0; s < deg; s += 32) {
        int m = deg - s; if (m > 32) m = 32;
        uint2 ev = make_uint2(0u, 0u);
        if (lane < m) ev = __ldg(&g_edges[base + s + lane]);   // coalesced meta load
        #pragma unroll 4
        for (int k = 0; k < m; ++k) {
            int   c = __shfl_sync(0xFFFFFFFFu, (int)ev.x, k);
            float v = __uint_as_float(__shfl_sync(0xFFFFFFFFu, (int)ev.y, k));
            float4 xv = __ldg(x4 + (size_t)c * VEC + lane);
            acc.x += v * xv.x; acc.y += v * xv.y;
            acc.z += v * xv.z; acc.w += v * xv.w;
        }
    }

    size_t oi = (size_t)r * VEC + lane;
    if (FINAL == 0) {
        reinterpret_cast<float4*>(y)[oi] = acc;   // stays hot in L2 for next layer
    } else {
        float4 a = __ldcs(reinterpret_cast<const float4*>(y1) + oi);  // y1: evict-first
        float4 b = __ldg (x4 + oi);                                   // y2 row: L2-hot
        acc.x += a.x + b.x; acc.y += a.y + b.y;
        acc.z += a.z + b.z; acc.w += a.w + b.w;
        __stcs(reinterpret_cast<float4*>(out) + oi, acc);             // out: streaming
    }
}

// ---------------------------------------------------------------------------
// Launcher
// ---------------------------------------------------------------------------
extern "C" void kernel_launch(void* const* d_in, const int* in_sizes, int n_in,
                              void* d_out, int out_size) {
    const float* embeds  = (const float*)d_in[0];
    const int*   adj_row = (const int*)d_in[1];
    const int*   adj_col = (const int*)d_in[2];
    const float* adj_val = (const float*)d_in[3];

    int n_nodes = in_sizes[0] / LATDIM;
    int n_edges = in_sizes[1];

    float* bufA = nullptr;
    float* bufB = nullptr;
    cudaGetSymbolAddress((void**)&bufA, g_bufA);
    cudaGetSymbolAddress((void**)&bufB, g_bufB);
    float* out = (float*)d_out;

    const int TPB = 256;
    int warp_blocks = (n_nodes * 32 + TPB - 1) / TPB;   // 1 warp per node
    int scan_blocks = (n_nodes + SCAN_B - 1) / SCAN_B;

    // LayerNorm: embeds -> bufA (x0)
    ln_kernel<<<warp_blocks, TPB>>>(embeds, bufA, n_nodes);

    // CSR build (reused by all 3 layers)
    zero_counts_kernel<<<(n_nodes + TPB - 1) / TPB, TPB>>>(n_nodes);
    hist_kernel<<<1024, TPB>>>(adj_row, n_edges);
    scan1_kernel<<<scan_blocks, SCAN_B>>>(n_nodes);
    scan2_kernel<<<1, SCAN_B>>>(scan_blocks);
    scatter_kernel<<<1024, TPB>>>(adj_row, adj_col, adj_val, n_edges);

    // Layer 1: y1 = A * x0          (bufA -> bufB)
    spmm_row_kernel<0><<<warp_blocks, TPB>>>(bufA, bufB, nullptr, nullptr, n_nodes);
    // Layer 2: y2 = A * y1          (bufB -> bufA)
    spmm_row_kernel<0><<<warp_blocks, TPB>>>(bufB, bufA, nullptr, nullptr, n_nodes);
    // Layer 3: out = A*y2 + y1 + y2 (gather bufA; add bufB row + bufA row)
    spmm_row_kernel<1><<<warp_blocks, TPB>>>(bufA, nullptr, bufB, out, n_nodes);
}